// round 10
// baseline (speedup 1.0000x reference)
#include <cuda_runtime.h>

// x: [32, 28, 28, 512] fp32 (only batch 0 used); out: [32, 29, 29, 1] fp32.
#define HH    28
#define WW    28
#define CC    512
#define NPOS  (HH * WW)      // 784
#define OD    29
#define PITCH 33             // odd pitch -> conflict-free smem chains
#define OUT2D (OD * OD)      // 841
#define BATCH 32
#define NPROD 49             // producer CTAs: 16 warps * 49 = 784 positions
#define NGRID (NPROD + BATCH)  // 81
#define NTHREADS 800         // consumers: 784 pollers; producers use 512

// One 8-byte slot per position: {hi32 = ready flag, lo32 = fsq bits}.
__device__ __align__(128) unsigned long long g_slot[NPOS];  // zero-initialized
__device__ __align__(128) unsigned int g_done = 0;

__global__ void __launch_bounds__(NTHREADS)
fused_kernel(const float* __restrict__ x, float* __restrict__ out) {
    const int tid = threadIdx.x;

    // ======================= PRODUCERS (blockIdx < 49) =====================
    if (blockIdx.x < NPROD) {
        if (tid >= 512) return;                 // idle warps leave immediately
        const int wid  = tid >> 5;
        const int lane = tid & 31;
        const int p    = blockIdx.x * 16 + wid; // one warp per position

        const float4* xp = reinterpret_cast<const float4*>(x + (size_t)p * CC);
        float s0, s1, s2, s3;
        {
            const float4 a = xp[lane];
            const float4 b = xp[32 + lane];
            const float4 c = xp[64 + lane];
            const float4 d = xp[96 + lane];
            s0 = (a.x * a.x + a.y * a.y) + (a.z * a.z + a.w * a.w);
            s1 = (b.x * b.x + b.y * b.y) + (b.z * b.z + b.w * b.w);
            s2 = (c.x * c.x + c.y * c.y) + (c.z * c.z + c.w * c.w);
            s3 = (d.x * d.x + d.y * d.y) + (d.z * d.z + d.w * d.w);
        }
        float s = (s0 + s1) + (s2 + s3);
        #pragma unroll
        for (int o = 16; o > 0; o >>= 1)        // portable 5-step butterfly
            s += __shfl_xor_sync(0xffffffffu, s, o);

        if (lane == 0) {                        // publish value+flag in ONE word
            const unsigned long long w =
                (1ull << 32) | (unsigned long long)__float_as_uint(s);
            asm volatile("st.global.release.gpu.b64 [%0], %1;"
                         :: "l"(&g_slot[p]), "l"(w) : "memory");
        }
        return;
    }

    // ======================= CONSUMERS (blockIdx 49..80) ===================
    const int b = blockIdx.x - NPROD;

    __shared__ float I[OD][PITCH];
    __shared__ unsigned int done_s;

    // Borders are data-independent: init before polling.
    if (tid < OD) { I[tid][0] = 0.f; I[0][tid] = 0.f; }

    // 784 parallel acquire-polls; the detecting load carries the value.
    if (tid < NPOS) {
        const int r = tid / WW, c = tid - r * WW;
        unsigned long long v;
        asm volatile("ld.global.acquire.gpu.b64 %0, [%1];"
                     : "=l"(v) : "l"(&g_slot[tid]) : "memory");
        while ((unsigned int)(v >> 32) == 0u) {
            asm volatile("ld.global.acquire.gpu.b64 %0, [%1];"
                         : "=l"(v) : "l"(&g_slot[tid]) : "memory");
        }
        I[r + 1][c + 1] = __uint_as_float((unsigned int)v);
    }
    __syncthreads();                            // all 784 values deposited

    if (tid == 0)                               // reset election, off hot path
        done_s = atomicAdd(&g_done, 1u);

    // Row cumsums in place (warp 0; stride-PITCH rows -> conflict-free).
    if (tid < HH) {
        float run = 0.f;
        #pragma unroll
        for (int c = 1; c <= WW; ++c) {
            run += I[tid + 1][c];
            I[tid + 1][c] = run;
        }
    }
    __syncwarp();
    // Column cumsums (warp 0; consecutive columns -> conflict-free).
    if (tid < WW) {
        const int c = tid + 1;
        float run = 0.f;
        #pragma unroll
        for (int r = 1; r <= HH; ++r) {
            run += I[r][c];
            I[r][c] = run;
        }
    }
    __syncthreads();

    // Box sums -> this consumer's batch slice (<=2 stores per thread).
    float* ob = out + (size_t)b * OUT2D;
    #pragma unroll
    for (int k = tid; k < OUT2D; k += NTHREADS) {
        const int i = k / OD, j = k - i * OD;
        const int r0 = min(max(HH / 2 - i, 0), HH);
        const int r1 = min(max(HH / 2 + HH - i, 0), HH);
        const int c0 = min(max(WW / 2 - j, 0), WW);
        const int c1 = min(max(WW / 2 + WW - j, 0), WW);
        ob[k] = I[r1][c1] - I[r0][c1] - I[r1][c0] + I[r0][c0];
    }

    // Last-joined consumer resets slots for the next graph replay. Safe:
    // its election (post-join) implies every consumer finished polling.
    // Vectorized: 392 x 16B stores (2 slots each).
    if (done_s == (unsigned int)(BATCH - 1)) {
        uint4* slots4 = reinterpret_cast<uint4*>(g_slot);
        if (tid < NPOS / 2)
            slots4[tid] = make_uint4(0u, 0u, 0u, 0u);
        if (tid == 0) g_done = 0u;
    }
}

extern "C" void kernel_launch(void* const* d_in, const int* in_sizes, int n_in,
                              void* d_out, int out_size) {
    const float* x = (const float*)d_in[0];
    float* out     = (float*)d_out;
    fused_kernel<<<NGRID, NTHREADS>>>(x, out);
}

// round 11
// speedup vs baseline: 1.2963x; 1.2963x over previous
#include <cuda_runtime.h>

// x: [32, 28, 28, 512] fp32 (only batch 0 used); out: [32, 29, 29, 1] fp32.
#define HH    28
#define WW    28
#define CC    512
#define NPOS  (HH * WW)      // 784
#define OD    29
#define PITCH 33             // odd pitch -> conflict-free smem chains
#define OUT2D (OD * OD)      // 841
#define BATCH 32
#define NPROD 49             // producer CTAs: 16 warps * 49 = 784 positions
#define NGRID (NPROD + BATCH)  // 81
#define NTHREADS 800         // consumers: 784 pollers; producers use 512

// One 8-byte slot per position: {hi32 = ready flag, lo32 = fsq bits}.
__device__ unsigned long long g_slot[NPOS];     // zero-initialized
__device__ __align__(128) unsigned int g_done = 0;

__global__ void __launch_bounds__(NTHREADS)
fused_kernel(const float* __restrict__ x, float* __restrict__ out) {
    const int tid = threadIdx.x;

    // ======================= PRODUCERS (blockIdx < 49) =====================
    if (blockIdx.x < NPROD) {
        if (tid >= 512) return;                 // idle warps leave immediately
        const int wid  = tid >> 5;
        const int lane = tid & 31;
        const int p    = blockIdx.x * 16 + wid; // one warp per position

        const float4* xp = reinterpret_cast<const float4*>(x + (size_t)p * CC);
        float s0, s1, s2, s3;
        {
            const float4 a = xp[lane];
            const float4 b = xp[32 + lane];
            const float4 c = xp[64 + lane];
            const float4 d = xp[96 + lane];
            s0 = (a.x * a.x + a.y * a.y) + (a.z * a.z + a.w * a.w);
            s1 = (b.x * b.x + b.y * b.y) + (b.z * b.z + b.w * b.w);
            s2 = (c.x * c.x + c.y * c.y) + (c.z * c.z + c.w * c.w);
            s3 = (d.x * d.x + d.y * d.y) + (d.z * d.z + d.w * d.w);
        }
        float s = (s0 + s1) + (s2 + s3);
        #pragma unroll
        for (int o = 16; o > 0; o >>= 1)        // portable 5-step butterfly
            s += __shfl_xor_sync(0xffffffffu, s, o);

        if (lane == 0) {                        // publish value+flag in ONE word
            const unsigned long long w =
                (1ull << 32) | (unsigned long long)__float_as_uint(s);
            asm volatile("st.global.release.gpu.b64 [%0], %1;"
                         :: "l"(&g_slot[p]), "l"(w) : "memory");
        }
        return;
    }

    // ======================= CONSUMERS (blockIdx 49..80) ===================
    const int b = blockIdx.x - NPROD;

    __shared__ float I[OD][PITCH];
    __shared__ unsigned int done_s;

    // Borders are data-independent: init before polling.
    if (tid < OD) { I[tid][0] = 0.f; I[0][tid] = 0.f; }

    // 784 parallel acquire-polls; the detecting load carries the value.
    if (tid < NPOS) {
        const int r = tid / WW, c = tid - r * WW;
        unsigned long long v;
        do {
            asm volatile("ld.global.acquire.gpu.b64 %0, [%1];"
                         : "=l"(v) : "l"(&g_slot[tid]) : "memory");
        } while ((unsigned int)(v >> 32) == 0u);
        I[r + 1][c + 1] = __uint_as_float((unsigned int)v);
    }
    __syncthreads();                            // all 784 values deposited

    if (tid == 0)                               // reset election, off hot path
        done_s = atomicAdd(&g_done, 1u);

    // Row cumsums in place (warp 0; stride-PITCH rows -> conflict-free).
    if (tid < HH) {
        float run = 0.f;
        #pragma unroll
        for (int c = 1; c <= WW; ++c) {
            run += I[tid + 1][c];
            I[tid + 1][c] = run;
        }
    }
    __syncwarp();
    // Column cumsums (warp 0; consecutive columns -> conflict-free).
    if (tid < WW) {
        const int c = tid + 1;
        float run = 0.f;
        #pragma unroll
        for (int r = 1; r <= HH; ++r) {
            run += I[r][c];
            I[r][c] = run;
        }
    }
    __syncthreads();

    // Box sums -> this consumer's batch slice (<=2 stores per thread).
    float* ob = out + (size_t)b * OUT2D;
    #pragma unroll
    for (int k = tid; k < OUT2D; k += NTHREADS) {
        const int i = k / OD, j = k - i * OD;
        const int r0 = min(max(HH / 2 - i, 0), HH);
        const int r1 = min(max(HH / 2 + HH - i, 0), HH);
        const int c0 = min(max(WW / 2 - j, 0), WW);
        const int c1 = min(max(WW / 2 + WW - j, 0), WW);
        ob[k] = I[r1][c1] - I[r0][c1] - I[r1][c0] + I[r0][c0];
    }

    // Last-joined consumer resets slots for the next graph replay. Safe:
    // its election (post-join) implies every consumer finished polling.
    if (done_s == (unsigned int)(BATCH - 1)) {
        if (tid < NPOS) g_slot[tid] = 0ull;
        if (tid == 0)   g_done = 0u;
    }
}

extern "C" void kernel_launch(void* const* d_in, const int* in_sizes, int n_in,
                              void* d_out, int out_size) {
    const float* x = (const float*)d_in[0];
    float* out     = (float*)d_out;
    fused_kernel<<<NGRID, NTHREADS>>>(x, out);
}